// round 3
// baseline (speedup 1.0000x reference)
#include <cuda_runtime.h>
#include <cuda_bf16.h>

// Problem constants
#define NN 50000
#define EE 800000
#define DD 128
#define LL 3
#define BB 256
#define BN_EPS 1e-5f
#define GEMM_GRID ((NN + 127) / 128)   // 391

// ---------------- scratch (static device globals; no allocation) ----------------
__device__ float g_bufA[(size_t)NN * DD];   // z: raw pre-BN2 layer output
__device__ float g_bufB[(size_t)NN * DD];   // agg (activated input to GEMM1)
__device__ float g_bufC[(size_t)NN * DD];   // y: raw pre-BN1 hidden
__device__ int   g_deg[NN];
__device__ int   g_rowstart[NN];
__device__ int   g_cursor[NN];
__device__ int   g_col[EE];
__device__ int   g_incl[NN];                // inclusive-scan temp
__device__ int   g_bsum[64];                // per-block sums for scan
__device__ int   g_bsumscan[64];
__device__ float g_partial_s[GEMM_GRID * DD];
__device__ float g_partial_q[GEMM_GRID * DD];
__device__ float g_scale1[DD];              // BN1: a = g * rsqrt(var+eps)
__device__ float g_shift1[DD];              // BN1: be - mean*a
__device__ float g_scale2[DD];              // BN2
__device__ float g_shift2[DD];

// ---------------- CSR build ----------------
__global__ void k_zero_deg() {
    int i = blockIdx.x * blockDim.x + threadIdx.x;
    if (i < NN) g_deg[i] = 0;
}

__global__ void k_hist(const int* __restrict__ dst) {
    int e = blockIdx.x * blockDim.x + threadIdx.x;
    if (e < EE) atomicAdd(&g_deg[dst[e]], 1);
}

// inclusive scan per 1024-block
__global__ void k_scan1() {
    __shared__ int s[1024];
    int t = threadIdx.x;
    int i = blockIdx.x * 1024 + t;
    int v = (i < NN) ? g_deg[i] : 0;
    s[t] = v;
    __syncthreads();
    #pragma unroll
    for (int off = 1; off < 1024; off <<= 1) {
        int add = (t >= off) ? s[t - off] : 0;
        __syncthreads();
        s[t] += add;
        __syncthreads();
    }
    if (i < NN) g_incl[i] = s[t];
    if (t == 1023) g_bsum[blockIdx.x] = s[t];
}

__global__ void k_scan2(int nblk) {
    __shared__ int s[64];
    int t = threadIdx.x;
    int v = (t < nblk) ? g_bsum[t] : 0;
    s[t] = v;
    __syncthreads();
    #pragma unroll
    for (int off = 1; off < 64; off <<= 1) {
        int add = (t >= off) ? s[t - off] : 0;
        __syncthreads();
        s[t] += add;
        __syncthreads();
    }
    g_bsumscan[t] = s[t];
}

__global__ void k_scan3() {
    int i = blockIdx.x * blockDim.x + threadIdx.x;
    if (i >= NN) return;
    int blk = i >> 10;
    int base = (blk > 0) ? g_bsumscan[blk - 1] : 0;
    int excl = base + g_incl[i] - g_deg[i];
    g_rowstart[i] = excl;
    g_cursor[i]   = excl;
}

__global__ void k_fill(const int* __restrict__ src, const int* __restrict__ dst) {
    int e = blockIdx.x * blockDim.x + threadIdx.x;
    if (e < EE) {
        int d = dst[e];
        int p = atomicAdd(&g_cursor[d], 1);
        g_col[p] = src[e];
    }
}

// ---------------- aggregation: one warp per node, CSR gather ----------------
// apply==0 (layer 0): H = X (already activated, no transform)
// apply==1          : H = g_bufA (raw z); act(v) = relu(scale2*v + shift2)
// writes g_bufB = act(h_self) + sum_{src->dst} act(h_src)
__global__ void k_aggregate(const float* __restrict__ X, int apply) {
    int warp = (blockIdx.x * blockDim.x + threadIdx.x) >> 5;
    int lane = threadIdx.x & 31;
    if (warp >= NN) return;
    const float4* H4 = apply ? (const float4*)g_bufA : (const float4*)X;

    float4 a4 = make_float4(1.f, 1.f, 1.f, 1.f);
    float4 s4 = make_float4(0.f, 0.f, 0.f, 0.f);
    if (apply) {
        a4 = *(const float4*)&g_scale2[lane * 4];
        s4 = *(const float4*)&g_shift2[lane * 4];
    }

    // self term (eps=0)
    float4 v = __ldg(&H4[(size_t)warp * 32 + lane]);
    float4 acc;
    if (apply) {
        acc.x = fmaxf(fmaf(v.x, a4.x, s4.x), 0.f);
        acc.y = fmaxf(fmaf(v.y, a4.y, s4.y), 0.f);
        acc.z = fmaxf(fmaf(v.z, a4.z, s4.z), 0.f);
        acc.w = fmaxf(fmaf(v.w, a4.w, s4.w), 0.f);
    } else {
        acc = v;
    }

    int s = g_rowstart[warp];
    int cnt = g_deg[warp];
    if (apply) {
        int j = 0;
        for (; j + 2 <= cnt; j += 2) {
            int s0 = g_col[s + j + 0];
            int s1 = g_col[s + j + 1];
            float4 v0 = __ldg(&H4[(size_t)s0 * 32 + lane]);
            float4 v1 = __ldg(&H4[(size_t)s1 * 32 + lane]);
            acc.x += fmaxf(fmaf(v0.x, a4.x, s4.x), 0.f) + fmaxf(fmaf(v1.x, a4.x, s4.x), 0.f);
            acc.y += fmaxf(fmaf(v0.y, a4.y, s4.y), 0.f) + fmaxf(fmaf(v1.y, a4.y, s4.y), 0.f);
            acc.z += fmaxf(fmaf(v0.z, a4.z, s4.z), 0.f) + fmaxf(fmaf(v1.z, a4.z, s4.z), 0.f);
            acc.w += fmaxf(fmaf(v0.w, a4.w, s4.w), 0.f) + fmaxf(fmaf(v1.w, a4.w, s4.w), 0.f);
        }
        for (; j < cnt; j++) {
            int s0 = g_col[s + j];
            float4 v0 = __ldg(&H4[(size_t)s0 * 32 + lane]);
            acc.x += fmaxf(fmaf(v0.x, a4.x, s4.x), 0.f);
            acc.y += fmaxf(fmaf(v0.y, a4.y, s4.y), 0.f);
            acc.z += fmaxf(fmaf(v0.z, a4.z, s4.z), 0.f);
            acc.w += fmaxf(fmaf(v0.w, a4.w, s4.w), 0.f);
        }
    } else {
        int j = 0;
        for (; j + 4 <= cnt; j += 4) {
            int s0 = g_col[s + j + 0];
            int s1 = g_col[s + j + 1];
            int s2 = g_col[s + j + 2];
            int s3 = g_col[s + j + 3];
            float4 v0 = __ldg(&H4[(size_t)s0 * 32 + lane]);
            float4 v1 = __ldg(&H4[(size_t)s1 * 32 + lane]);
            float4 v2 = __ldg(&H4[(size_t)s2 * 32 + lane]);
            float4 v3 = __ldg(&H4[(size_t)s3 * 32 + lane]);
            acc.x += v0.x + v1.x + v2.x + v3.x;
            acc.y += v0.y + v1.y + v2.y + v3.y;
            acc.z += v0.z + v1.z + v2.z + v3.z;
            acc.w += v0.w + v1.w + v2.w + v3.w;
        }
        for (; j < cnt; j++) {
            int s0 = g_col[s + j];
            float4 v0 = __ldg(&H4[(size_t)s0 * 32 + lane]);
            acc.x += v0.x; acc.y += v0.y; acc.z += v0.z; acc.w += v0.w;
        }
    }
    ((float4*)g_bufB)[(size_t)warp * 32 + lane] = acc;
}

// ---------------- SGEMM + fused BN-stats epilogue ----------------
// which==0: A=g_bufB (no input transform),                 C=g_bufC
// which==1: A=g_bufC with act(v)=relu(scale1*v+shift1),    C=g_bufA
// Epilogue: per-block column sum/sumsq of C tile -> g_partial_s/q[block].
// BM=128, BN=128, BK=8, 256 threads, 8x8 per thread
__global__ __launch_bounds__(256, 2)
void k_gemm_stats(const float* __restrict__ W, const float* __restrict__ bias, int which) {
    const float* __restrict__ A = which ? g_bufC : g_bufB;
    float* __restrict__ C       = which ? g_bufA : g_bufC;

    __shared__ float As[8][128];
    __shared__ float Bs[8][128];
    __shared__ float s_s[16][128];
    __shared__ float s_q[16][128];

    int t = threadIdx.x;
    int block_row = blockIdx.x * 128;

    int tx = t & 15, ty = t >> 4;
    int m0 = ty * 8, n0 = tx * 8;

    int arow = t >> 1;
    int acol = (t & 1) * 4;
    int brow = t >> 5;
    int bcol = (t & 31) * 4;

    float acc[8][8];
    #pragma unroll
    for (int i = 0; i < 8; i++)
        #pragma unroll
        for (int j = 0; j < 8; j++) acc[i][j] = 0.f;

    int gr_a = block_row + arow;
    bool a_ok = (gr_a < NN);
    const float4* Arow = (const float4*)(A + (size_t)gr_a * 128);

    for (int k0 = 0; k0 < 128; k0 += 8) {
        float4 av = a_ok ? __ldg(&Arow[(k0 + acol) >> 2]) : make_float4(0.f, 0.f, 0.f, 0.f);
        if (which) {
            // fused BN1 affine + ReLU on the A operand (per-k scale)
            float4 sc = *(const float4*)&g_scale1[k0 + acol];
            float4 sh = *(const float4*)&g_shift1[k0 + acol];
            av.x = fmaxf(fmaf(av.x, sc.x, sh.x), 0.f);
            av.y = fmaxf(fmaf(av.y, sc.y, sh.y), 0.f);
            av.z = fmaxf(fmaf(av.z, sc.z, sh.z), 0.f);
            av.w = fmaxf(fmaf(av.w, sc.w, sh.w), 0.f);
        }
        As[acol + 0][arow] = av.x;
        As[acol + 1][arow] = av.y;
        As[acol + 2][arow] = av.z;
        As[acol + 3][arow] = av.w;
        float4 bv = __ldg((const float4*)(W + (size_t)(k0 + brow) * 128 + bcol));
        *(float4*)(&Bs[brow][bcol]) = bv;
        __syncthreads();
        #pragma unroll
        for (int k = 0; k < 8; k++) {
            float4 ra0 = *(const float4*)(&As[k][m0]);
            float4 ra1 = *(const float4*)(&As[k][m0 + 4]);
            float4 rb0 = *(const float4*)(&Bs[k][n0]);
            float4 rb1 = *(const float4*)(&Bs[k][n0 + 4]);
            float ra[8] = {ra0.x, ra0.y, ra0.z, ra0.w, ra1.x, ra1.y, ra1.z, ra1.w};
            float rb[8] = {rb0.x, rb0.y, rb0.z, rb0.w, rb1.x, rb1.y, rb1.z, rb1.w};
            #pragma unroll
            for (int i = 0; i < 8; i++)
                #pragma unroll
                for (int j = 0; j < 8; j++)
                    acc[i][j] += ra[i] * rb[j];
        }
        __syncthreads();
    }

    // epilogue: bias add, store, and per-column partial stats (valid rows only)
    float bj[8];
    #pragma unroll
    for (int j = 0; j < 8; j++) bj[j] = __ldg(&bias[n0 + j]);

    float col_s[8], col_q[8];
    #pragma unroll
    for (int j = 0; j < 8; j++) { col_s[j] = 0.f; col_q[j] = 0.f; }

    #pragma unroll
    for (int i = 0; i < 8; i++) {
        int gr = block_row + m0 + i;
        if (gr < NN) {
            float o[8];
            #pragma unroll
            for (int j = 0; j < 8; j++) {
                o[j] = acc[i][j] + bj[j];
                col_s[j] += o[j];
                col_q[j] += o[j] * o[j];
            }
            #pragma unroll
            for (int j = 0; j < 8; j += 4) {
                float4 ov = make_float4(o[j], o[j + 1], o[j + 2], o[j + 3]);
                *(float4*)(C + (size_t)gr * 128 + n0 + j) = ov;
            }
        }
    }

    #pragma unroll
    for (int j = 0; j < 8; j++) {
        s_s[ty][n0 + j] = col_s[j];
        s_q[ty][n0 + j] = col_q[j];
    }
    __syncthreads();
    if (t < 128) {
        float s = 0.f, q = 0.f;
        #pragma unroll
        for (int r = 0; r < 16; r++) {
            s += s_s[r][t];
            q += s_q[r][t];
        }
        g_partial_s[blockIdx.x * DD + t] = s;
        g_partial_q[blockIdx.x * DD + t] = q;
    }
}

// ---------------- BN finalize: reduce partials -> scale/shift ----------------
// which==0 -> scale1/shift1 ; which==1 -> scale2/shift2
__global__ void k_finalize(const float* __restrict__ gamma, const float* __restrict__ beta,
                           int which) {
    int c = threadIdx.x;
    float s = 0.f, q = 0.f;
    for (int b = 0; b < GEMM_GRID; b++) {
        s += g_partial_s[b * DD + c];
        q += g_partial_q[b * DD + c];
    }
    float inv_n = 1.f / (float)NN;
    float mean = s * inv_n;
    float var  = q * inv_n - mean * mean;
    float a = gamma[c] * rsqrtf(var + BN_EPS);
    float sh = beta[c] - mean * a;
    if (which) { g_scale2[c] = a; g_shift2[c] = sh; }
    else       { g_scale1[c] = a; g_shift1[c] = sh; }
}

// ---------------- global add pool (batch sorted -> run-length accumulate) -------
// reads raw z in g_bufA, applies act2 on the fly
__global__ void k_pool(const int* __restrict__ batch, float* __restrict__ out) {
    int c = threadIdx.x & 127;
    int half = threadIdx.x >> 7;
    int r0 = blockIdx.x * 64;
    int rend = min(r0 + 64, NN);
    float a = g_scale2[c];
    float s2 = g_shift2[c];
    int cur = -1;
    float acc = 0.f;
    for (int r = r0 + half; r < rend; r += 2) {
        int b = batch[r];
        if (b != cur) {
            if (cur >= 0) atomicAdd(&out[(size_t)cur * 128 + c], acc);
            cur = b;
            acc = 0.f;
        }
        float v = g_bufA[(size_t)r * 128 + c];
        acc += fmaxf(fmaf(v, a, s2), 0.f);
    }
    if (cur >= 0) atomicAdd(&out[(size_t)cur * 128 + c], acc);
}

// ---------------- launch ----------------
extern "C" void kernel_launch(void* const* d_in, const int* in_sizes, int n_in,
                              void* d_out, int out_size) {
    const float* x      = (const float*)d_in[0];
    const int*   eidx   = (const int*)d_in[1];
    const int*   batch  = (const int*)d_in[2];
    const float* W1     = (const float*)d_in[3];
    const float* b1     = (const float*)d_in[4];
    const float* g1     = (const float*)d_in[5];
    const float* be1    = (const float*)d_in[6];
    const float* W2     = (const float*)d_in[7];
    const float* b2     = (const float*)d_in[8];
    const float* g2     = (const float*)d_in[9];
    const float* be2    = (const float*)d_in[10];
    float* out = (float*)d_out;

    const int* src = eidx;
    const int* dst = eidx + EE;

    const int nscanblk = (NN + 1023) / 1024;   // 49
    const int agg_grid = (NN + 7) / 8;         // 6250 (8 warps/block)

    // --- CSR build (reused for all 3 layers) ---
    k_zero_deg<<<(NN + 255) / 256, 256>>>();
    k_hist<<<(EE + 255) / 256, 256>>>(dst);
    k_scan1<<<nscanblk, 1024>>>();
    k_scan2<<<1, 64>>>(nscanblk);
    k_scan3<<<(NN + 255) / 256, 256>>>();
    k_fill<<<(EE + 255) / 256, 256>>>(src, dst);

    for (int i = 0; i < LL; i++) {
        // bufB = act(h) + gathered act(h[src])   (layer 0: act = identity on x)
        k_aggregate<<<agg_grid, 256>>>(x, i > 0 ? 1 : 0);
        // bufC = bufB @ W1[i] + b1[i]  (+BN1 stats)
        k_gemm_stats<<<GEMM_GRID, 256>>>(W1 + (size_t)i * DD * DD, b1 + i * DD, 0);
        k_finalize<<<1, 128>>>(g1 + i * DD, be1 + i * DD, 0);
        // bufA = act1(bufC) @ W2[i] + b2[i]  (+BN2 stats)
        k_gemm_stats<<<GEMM_GRID, 256>>>(W2 + (size_t)i * DD * DD, b2 + i * DD, 1);
        k_finalize<<<1, 128>>>(g2 + i * DD, be2 + i * DD, 1);
    }

    // --- global add pool: out = segment_sum(act2(bufA), batch) ---
    cudaMemsetAsync(out, 0, (size_t)BB * DD * sizeof(float));
    k_pool<<<(NN + 63) / 64, 256>>>(batch, out);
}

// round 5
// speedup vs baseline: 1.4835x; 1.4835x over previous
#include <cuda_runtime.h>
#include <cuda_bf16.h>
#include <cstdint>

// Problem constants
#define NN 50000
#define EE 800000
#define DD 128
#define LL 3
#define BB 256
#define BN_EPS 1e-5f
#define GEMM_GRID ((NN + 127) / 128)   // 391

// smem layout for tensor GEMM (bf16 tiles, 256B row pitch, xor-swizzled chunks)
#define SM_AHI 0
#define SM_ALO 32768
#define SM_BHI 65536
#define SM_BLO 98304
#define SMEM_TOT 131072

// ---------------- scratch (static device globals; no allocation) ----------------
__device__ float g_bufA[(size_t)NN * DD];   // z: raw pre-BN2 layer output
__device__ float g_bufB[(size_t)NN * DD];   // agg (activated input to GEMM1)
__device__ float g_bufC[(size_t)NN * DD];   // y: raw pre-BN1 hidden
__device__ int   g_deg[NN];
__device__ int   g_rowstart[NN];
__device__ int   g_cursor[NN];
__device__ int   g_col[EE];
__device__ int   g_incl[NN];
__device__ int   g_bsum[64];
__device__ int   g_bsumscan[64];
__device__ float g_partial_s[GEMM_GRID * DD];
__device__ float g_partial_q[GEMM_GRID * DD];
__device__ float g_scale1[DD];
__device__ float g_shift1[DD];
__device__ float g_scale2[DD];
__device__ float g_shift2[DD];
// prepared weights: [layer*2+which][hi/lo][32KB tile as uint4], swizzled [k][n] layout
__device__ uint4 g_wt[6][2][2048];

// ---------------- helpers ----------------
__device__ __forceinline__ uint32_t smem_u32(const void* p) {
    uint32_t a;
    asm("{ .reg .u64 t; cvta.to.shared.u64 t, %1; cvt.u32.u64 %0, t; }" : "=r"(a) : "l"(p));
    return a;
}

// byte offset inside a 128x128 bf16 tile (256B rows, 16B chunks, xor swizzle)
__device__ __forceinline__ uint32_t swz(int row, int col8) {
    // col8 = column index (multiple of 8 bf16)
    int chunk = col8 >> 3;
    return (uint32_t)(row * 256 + ((chunk ^ (row & 7)) << 4));
}

// split fp32 pair -> bf16x2 hi + bf16x2 lo
__device__ __forceinline__ void split2(float a, float b, uint32_t& hi, uint32_t& lo) {
    __nv_bfloat162 h = __floats2bfloat162_rn(a, b);
    uint32_t uh = *reinterpret_cast<uint32_t*>(&h);
    float ra = __uint_as_float((uh & 0xFFFFu) << 16);
    float rb = __uint_as_float(uh & 0xFFFF0000u);
    __nv_bfloat162 l = __floats2bfloat162_rn(a - ra, b - rb);
    hi = uh;
    lo = *reinterpret_cast<uint32_t*>(&l);
}

__device__ __forceinline__ void ldsm_x4(uint32_t addr, uint32_t& r0, uint32_t& r1,
                                        uint32_t& r2, uint32_t& r3) {
    asm volatile("ldmatrix.sync.aligned.m8n8.x4.shared.b16 {%0,%1,%2,%3}, [%4];"
                 : "=r"(r0), "=r"(r1), "=r"(r2), "=r"(r3) : "r"(addr));
}

__device__ __forceinline__ void ldsm_x4_t(uint32_t addr, uint32_t& r0, uint32_t& r1,
                                          uint32_t& r2, uint32_t& r3) {
    asm volatile("ldmatrix.sync.aligned.m8n8.x4.trans.shared.b16 {%0,%1,%2,%3}, [%4];"
                 : "=r"(r0), "=r"(r1), "=r"(r2), "=r"(r3) : "r"(addr));
}

__device__ __forceinline__ void mma_bf16(float* c, uint32_t a0, uint32_t a1, uint32_t a2,
                                         uint32_t a3, uint32_t b0, uint32_t b1) {
    asm volatile(
        "mma.sync.aligned.m16n8k16.row.col.f32.bf16.bf16.f32 "
        "{%0,%1,%2,%3}, {%4,%5,%6,%7}, {%8,%9}, {%0,%1,%2,%3};"
        : "+f"(c[0]), "+f"(c[1]), "+f"(c[2]), "+f"(c[3])
        : "r"(a0), "r"(a1), "r"(a2), "r"(a3), "r"(b0), "r"(b1));
}

// ---------------- CSR build ----------------
__global__ void k_zero_deg() {
    int i = blockIdx.x * blockDim.x + threadIdx.x;
    if (i < NN) g_deg[i] = 0;
}

__global__ void k_hist(const int* __restrict__ dst) {
    int e = blockIdx.x * blockDim.x + threadIdx.x;
    if (e < EE) atomicAdd(&g_deg[dst[e]], 1);
}

__global__ void k_scan1() {
    __shared__ int s[1024];
    int t = threadIdx.x;
    int i = blockIdx.x * 1024 + t;
    int v = (i < NN) ? g_deg[i] : 0;
    s[t] = v;
    __syncthreads();
    #pragma unroll
    for (int off = 1; off < 1024; off <<= 1) {
        int add = (t >= off) ? s[t - off] : 0;
        __syncthreads();
        s[t] += add;
        __syncthreads();
    }
    if (i < NN) g_incl[i] = s[t];
    if (t == 1023) g_bsum[blockIdx.x] = s[t];
}

__global__ void k_scan2(int nblk) {
    __shared__ int s[64];
    int t = threadIdx.x;
    int v = (t < nblk) ? g_bsum[t] : 0;
    s[t] = v;
    __syncthreads();
    #pragma unroll
    for (int off = 1; off < 64; off <<= 1) {
        int add = (t >= off) ? s[t - off] : 0;
        __syncthreads();
        s[t] += add;
        __syncthreads();
    }
    g_bsumscan[t] = s[t];
}

__global__ void k_scan3() {
    int i = blockIdx.x * blockDim.x + threadIdx.x;
    if (i >= NN) return;
    int blk = i >> 10;
    int base = (blk > 0) ? g_bsumscan[blk - 1] : 0;
    int excl = base + g_incl[i] - g_deg[i];
    g_rowstart[i] = excl;
    g_cursor[i]   = excl;
}

__global__ void k_fill(const int* __restrict__ src, const int* __restrict__ dst) {
    int e = blockIdx.x * blockDim.x + threadIdx.x;
    if (e < EE) {
        int d = dst[e];
        int p = atomicAdd(&g_cursor[d], 1);
        g_col[p] = src[e];
    }
}

// ---------------- aggregation: one warp per node, CSR gather ----------------
__global__ void k_aggregate(const float* __restrict__ X, int apply) {
    int warp = (blockIdx.x * blockDim.x + threadIdx.x) >> 5;
    int lane = threadIdx.x & 31;
    if (warp >= NN) return;
    const float4* H4 = apply ? (const float4*)g_bufA : (const float4*)X;

    float4 a4 = make_float4(1.f, 1.f, 1.f, 1.f);
    float4 s4 = make_float4(0.f, 0.f, 0.f, 0.f);
    if (apply) {
        a4 = *(const float4*)&g_scale2[lane * 4];
        s4 = *(const float4*)&g_shift2[lane * 4];
    }

    float4 v = __ldg(&H4[(size_t)warp * 32 + lane]);
    float4 acc;
    if (apply) {
        acc.x = fmaxf(fmaf(v.x, a4.x, s4.x), 0.f);
        acc.y = fmaxf(fmaf(v.y, a4.y, s4.y), 0.f);
        acc.z = fmaxf(fmaf(v.z, a4.z, s4.z), 0.f);
        acc.w = fmaxf(fmaf(v.w, a4.w, s4.w), 0.f);
    } else {
        acc = v;
    }

    int s = g_rowstart[warp];
    int cnt = g_deg[warp];
    if (apply) {
        int j = 0;
        for (; j + 2 <= cnt; j += 2) {
            int s0 = g_col[s + j + 0];
            int s1 = g_col[s + j + 1];
            float4 v0 = __ldg(&H4[(size_t)s0 * 32 + lane]);
            float4 v1 = __ldg(&H4[(size_t)s1 * 32 + lane]);
            acc.x += fmaxf(fmaf(v0.x, a4.x, s4.x), 0.f) + fmaxf(fmaf(v1.x, a4.x, s4.x), 0.f);
            acc.y += fmaxf(fmaf(v0.y, a4.y, s4.y), 0.f) + fmaxf(fmaf(v1.y, a4.y, s4.y), 0.f);
            acc.z += fmaxf(fmaf(v0.z, a4.z, s4.z), 0.f) + fmaxf(fmaf(v1.z, a4.z, s4.z), 0.f);
            acc.w += fmaxf(fmaf(v0.w, a4.w, s4.w), 0.f) + fmaxf(fmaf(v1.w, a4.w, s4.w), 0.f);
        }
        for (; j < cnt; j++) {
            int s0 = g_col[s + j];
            float4 v0 = __ldg(&H4[(size_t)s0 * 32 + lane]);
            acc.x += fmaxf(fmaf(v0.x, a4.x, s4.x), 0.f);
            acc.y += fmaxf(fmaf(v0.y, a4.y, s4.y), 0.f);
            acc.z += fmaxf(fmaf(v0.z, a4.z, s4.z), 0.f);
            acc.w += fmaxf(fmaf(v0.w, a4.w, s4.w), 0.f);
        }
    } else {
        int j = 0;
        for (; j + 4 <= cnt; j += 4) {
            int s0 = g_col[s + j + 0];
            int s1 = g_col[s + j + 1];
            int s2 = g_col[s + j + 2];
            int s3 = g_col[s + j + 3];
            float4 v0 = __ldg(&H4[(size_t)s0 * 32 + lane]);
            float4 v1 = __ldg(&H4[(size_t)s1 * 32 + lane]);
            float4 v2 = __ldg(&H4[(size_t)s2 * 32 + lane]);
            float4 v3 = __ldg(&H4[(size_t)s3 * 32 + lane]);
            acc.x += v0.x + v1.x + v2.x + v3.x;
            acc.y += v0.y + v1.y + v2.y + v3.y;
            acc.z += v0.z + v1.z + v2.z + v3.z;
            acc.w += v0.w + v1.w + v2.w + v3.w;
        }
        for (; j < cnt; j++) {
            int s0 = g_col[s + j];
            float4 v0 = __ldg(&H4[(size_t)s0 * 32 + lane]);
            acc.x += v0.x; acc.y += v0.y; acc.z += v0.z; acc.w += v0.w;
        }
    }
    ((float4*)g_bufB)[(size_t)warp * 32 + lane] = acc;
}

// ---------------- W prep: bf16 split + swizzled [k][n] layout ----------------
// one block per (layer, which): idx = layer*2 + which. B operand is k-major = W natural.
__global__ void k_prep_w(const float* __restrict__ W1, const float* __restrict__ W2) {
    int idx = blockIdx.x;
    int layer = idx >> 1, which = idx & 1;
    const float* src = (which ? W2 : W1) + (size_t)layer * DD * DD;
    int t = threadIdx.x;
    int row = t >> 1, half = t & 1;    // row = k index

    char* dh = (char*)&g_wt[idx][0][0];
    char* dl = (char*)&g_wt[idx][1][0];
    const float4* s4 = (const float4*)(src + (size_t)row * 128 + half * 64);
    #pragma unroll
    for (int g = 0; g < 8; g++) {
        int cbase = half * 64 + g * 8;     // n index
        float4 u = __ldg(&s4[2 * g + 0]);
        float4 v = __ldg(&s4[2 * g + 1]);
        uint32_t h0, h1, h2, h3, l0, l1, l2, l3;
        split2(u.x, u.y, h0, l0);
        split2(u.z, u.w, h1, l1);
        split2(v.x, v.y, h2, l2);
        split2(v.z, v.w, h3, l3);
        uint32_t off = swz(row, cbase);
        *(uint4*)(dh + off) = make_uint4(h0, h1, h2, h3);
        *(uint4*)(dl + off) = make_uint4(l0, l1, l2, l3);
    }
}

// ---------------- tensor-core GEMM (mma.sync bf16 3-term): C = act?(A) @ W + bias --
// which==0: A=g_bufB (no transform), C=g_bufC
// which==1: A=g_bufC with relu(scale1*v+shift1), C=g_bufA
__global__ __launch_bounds__(256, 1)
void k_gemm_mma(const float* __restrict__ bias, int widx, int which) {
    extern __shared__ char smem[];
    uint32_t sb = smem_u32(smem);
    const float* __restrict__ A = which ? g_bufC : g_bufB;
    float* __restrict__ C       = which ? g_bufA : g_bufC;

    int t = threadIdx.x;
    int wid = t >> 5, lane = t & 31;
    int block_row = blockIdx.x * 128;

    // --- B copy (pre-swizzled bytes) ---
    {
        const uint4* bh = &g_wt[widx][0][0];
        const uint4* bl = &g_wt[widx][1][0];
        uint4* sh4 = (uint4*)(smem + SM_BHI);
        uint4* sl4 = (uint4*)(smem + SM_BLO);
        #pragma unroll
        for (int i = 0; i < 8; i++) {
            sh4[t + 256 * i] = __ldg(&bh[t + 256 * i]);
            sl4[t + 256 * i] = __ldg(&bl[t + 256 * i]);
        }
    }

    // --- A convert: fp32 -> split bf16, swizzled ---
    {
        int row = t >> 1, half = t & 1;
        int gr = block_row + row;
        bool ok = (gr < NN);
        const float4* a4 = (const float4*)(A + (size_t)gr * 128 + half * 64);
        #pragma unroll
        for (int g = 0; g < 8; g++) {
            int cbase = half * 64 + g * 8;
            float4 u = ok ? __ldg(&a4[2 * g + 0]) : make_float4(0.f, 0.f, 0.f, 0.f);
            float4 v = ok ? __ldg(&a4[2 * g + 1]) : make_float4(0.f, 0.f, 0.f, 0.f);
            if (which) {
                float4 sa  = *(const float4*)&g_scale1[cbase];
                float4 sh4 = *(const float4*)&g_shift1[cbase];
                float4 sa2 = *(const float4*)&g_scale1[cbase + 4];
                float4 sh2 = *(const float4*)&g_shift1[cbase + 4];
                u.x = fmaxf(fmaf(u.x, sa.x, sh4.x), 0.f);
                u.y = fmaxf(fmaf(u.y, sa.y, sh4.y), 0.f);
                u.z = fmaxf(fmaf(u.z, sa.z, sh4.z), 0.f);
                u.w = fmaxf(fmaf(u.w, sa.w, sh4.w), 0.f);
                v.x = fmaxf(fmaf(v.x, sa2.x, sh2.x), 0.f);
                v.y = fmaxf(fmaf(v.y, sa2.y, sh2.y), 0.f);
                v.z = fmaxf(fmaf(v.z, sa2.z, sh2.z), 0.f);
                v.w = fmaxf(fmaf(v.w, sa2.w, sh2.w), 0.f);
            }
            uint32_t h0, h1, h2, h3, l0, l1, l2, l3;
            split2(u.x, u.y, h0, l0);
            split2(u.z, u.w, h1, l1);
            split2(v.x, v.y, h2, l2);
            split2(v.z, v.w, h3, l3);
            uint32_t off = swz(row, cbase);
            *(uint4*)(smem + SM_AHI + off) = make_uint4(h0, h1, h2, h3);
            *(uint4*)(smem + SM_ALO + off) = make_uint4(l0, l1, l2, l3);
        }
    }
    __syncthreads();

    // --- MMA mainloop: warp tile 32x64; 3 terms (AhiBhi, AhiBlo, AloBhi) ---
    int wm = (wid & 3) * 32;         // warp row offset in tile
    int wn = (wid >> 2) * 64;        // warp col offset in tile
    float acc[2][8][4];
    #pragma unroll
    for (int mt = 0; mt < 2; mt++)
        #pragma unroll
        for (int nt = 0; nt < 8; nt++)
            #pragma unroll
            for (int q = 0; q < 4; q++) acc[mt][nt][q] = 0.f;

    const uint32_t aoff[3] = { SM_AHI, SM_AHI, SM_ALO };
    const uint32_t boff[3] = { SM_BHI, SM_BLO, SM_BHI };

    for (int tt = 0; tt < 3; tt++) {
        uint32_t sA = sb + aoff[tt];
        uint32_t sB = sb + boff[tt];
        #pragma unroll
        for (int ks = 0; ks < 8; ks++) {
            // A fragments: 2 m-tiles of 16x16
            uint32_t af[2][4];
            #pragma unroll
            for (int mt = 0; mt < 2; mt++) {
                int r = wm + mt * 16 + (lane & 15);
                int chunk = ks * 2 + (lane >> 4);
                uint32_t addr = sA + (uint32_t)(r * 256 + ((chunk ^ (r & 7)) << 4));
                ldsm_x4(addr, af[mt][0], af[mt][1], af[mt][2], af[mt][3]);
            }
            // B fragments: 4 n-pairs (each = two n-tiles of 16x8), k-major + trans
            uint32_t bf[8][2];
            #pragma unroll
            for (int np = 0; np < 4; np++) {
                int r = ks * 16 + (lane & 15);
                int chunk = ((wn + np * 16) >> 3) + (lane >> 4);
                uint32_t addr = sB + (uint32_t)(r * 256 + ((chunk ^ (r & 7)) << 4));
                uint32_t b0, b1, b2, b3;
                ldsm_x4_t(addr, b0, b1, b2, b3);
                bf[np * 2 + 0][0] = b0; bf[np * 2 + 0][1] = b1;
                bf[np * 2 + 1][0] = b2; bf[np * 2 + 1][1] = b3;
            }
            #pragma unroll
            for (int mt = 0; mt < 2; mt++)
                #pragma unroll
                for (int nt = 0; nt < 8; nt++)
                    mma_bf16(acc[mt][nt], af[mt][0], af[mt][1], af[mt][2], af[mt][3],
                             bf[nt][0], bf[nt][1]);
        }
    }

    // --- epilogue: bias add + store ---
    {
        int quad = lane >> 2, tq = lane & 3;
        #pragma unroll
        for (int mt = 0; mt < 2; mt++) {
            int r0 = block_row + wm + mt * 16 + quad;
            #pragma unroll
            for (int nt = 0; nt < 8; nt++) {
                int c = wn + nt * 8 + tq * 2;
                float bx = __ldg(&bias[c]);
                float by = __ldg(&bias[c + 1]);
                if (r0 < NN) {
                    float2 o = make_float2(acc[mt][nt][0] + bx, acc[mt][nt][1] + by);
                    *(float2*)(C + (size_t)r0 * 128 + c) = o;
                }
                if (r0 + 8 < NN) {
                    float2 o = make_float2(acc[mt][nt][2] + bx, acc[mt][nt][3] + by);
                    *(float2*)(C + (size_t)(r0 + 8) * 128 + c) = o;
                }
            }
        }
    }
}

// ---------------- column stats over node axis (per-block partials) --------------
__global__ void k_stats(int which) {
    const float* __restrict__ Y = which ? g_bufA : g_bufC;
    __shared__ float sh_s[256];
    __shared__ float sh_q[256];
    int c = threadIdx.x & 127;
    int half = threadIdx.x >> 7;
    int r0 = blockIdx.x * 128;
    int rend = min(r0 + 128, NN);
    float s = 0.f, q = 0.f;
    for (int r = r0 + half; r < rend; r += 2) {
        float v = Y[(size_t)r * 128 + c];
        s += v;
        q += v * v;
    }
    sh_s[threadIdx.x] = s;
    sh_q[threadIdx.x] = q;
    __syncthreads();
    if (half == 0) {
        g_partial_s[blockIdx.x * DD + c] = s + sh_s[128 + c];
        g_partial_q[blockIdx.x * DD + c] = q + sh_q[128 + c];
    }
}

__global__ void k_finalize(const float* __restrict__ gamma, const float* __restrict__ beta,
                           int which) {
    __shared__ float ss[512];
    __shared__ float sq[512];
    int t = threadIdx.x;
    int c = t & 127, seg = t >> 7;
    float s = 0.f, q = 0.f;
    for (int b = seg; b < GEMM_GRID; b += 4) {
        s += g_partial_s[b * DD + c];
        q += g_partial_q[b * DD + c];
    }
    ss[t] = s; sq[t] = q;
    __syncthreads();
    if (seg == 0) {
        s = ss[c] + ss[c + 128] + ss[c + 256] + ss[c + 384];
        q = sq[c] + sq[c + 128] + sq[c + 256] + sq[c + 384];
        float inv_n = 1.f / (float)NN;
        float mean = s * inv_n;
        float var  = q * inv_n - mean * mean;
        float a = gamma[c] * rsqrtf(var + BN_EPS);
        float sh = beta[c] - mean * a;
        if (which) { g_scale2[c] = a; g_shift2[c] = sh; }
        else       { g_scale1[c] = a; g_shift1[c] = sh; }
    }
}

// ---------------- global add pool (batch sorted -> run-length accumulate) -------
__global__ void k_pool(const int* __restrict__ batch, float* __restrict__ out) {
    int c = threadIdx.x & 127;
    int half = threadIdx.x >> 7;
    int r0 = blockIdx.x * 64;
    int rend = min(r0 + 64, NN);
    float a = g_scale2[c];
    float s2 = g_shift2[c];
    int cur = -1;
    float acc = 0.f;
    for (int r = r0 + half; r < rend; r += 2) {
        int b = batch[r];
        if (b != cur) {
            if (cur >= 0) atomicAdd(&out[(size_t)cur * 128 + c], acc);
            cur = b;
            acc = 0.f;
        }
        float v = g_bufA[(size_t)r * 128 + c];
        acc += fmaxf(fmaf(v, a, s2), 0.f);
    }
    if (cur >= 0) atomicAdd(&out[(size_t)cur * 128 + c], acc);
}

// ---------------- launch ----------------
extern "C" void kernel_launch(void* const* d_in, const int* in_sizes, int n_in,
                              void* d_out, int out_size) {
    const float* x      = (const float*)d_in[0];
    const int*   eidx   = (const int*)d_in[1];
    const int*   batch  = (const int*)d_in[2];
    const float* W1     = (const float*)d_in[3];
    const float* b1     = (const float*)d_in[4];
    const float* g1     = (const float*)d_in[5];
    const float* be1    = (const float*)d_in[6];
    const float* W2     = (const float*)d_in[7];
    const float* b2     = (const float*)d_in[8];
    const float* g2     = (const float*)d_in[9];
    const float* be2    = (const float*)d_in[10];
    float* out = (float*)d_out;

    const int* src = eidx;
    const int* dst = eidx + EE;

    cudaFuncSetAttribute(k_gemm_mma, cudaFuncAttributeMaxDynamicSharedMemorySize, SMEM_TOT);

    const int nscanblk = (NN + 1023) / 1024;   // 49
    const int agg_grid = (NN + 7) / 8;         // 6250

    // --- weight prep + CSR build (reused for all 3 layers) ---
    k_prep_w<<<6, 256>>>(W1, W2);
    k_zero_deg<<<(NN + 255) / 256, 256>>>();
    k_hist<<<(EE + 255) / 256, 256>>>(dst);
    k_scan1<<<nscanblk, 1024>>>();
    k_scan2<<<1, 64>>>(nscanblk);
    k_scan3<<<(NN + 255) / 256, 256>>>();
    k_fill<<<(EE + 255) / 256, 256>>>(src, dst);

    for (int i = 0; i < LL; i++) {
        k_aggregate<<<agg_grid, 256>>>(x, i > 0 ? 1 : 0);
        k_gemm_mma<<<GEMM_GRID, 256, SMEM_TOT>>>(b1 + i * DD, i * 2 + 0, 0);
        k_stats<<<GEMM_GRID, 256>>>(0);
        k_finalize<<<1, 512>>>(g1 + i * DD, be1 + i * DD, 0);
        k_gemm_mma<<<GEMM_GRID, 256, SMEM_TOT>>>(b2 + i * DD, i * 2 + 1, 1);
        k_stats<<<GEMM_GRID, 256>>>(1);
        k_finalize<<<1, 512>>>(g2 + i * DD, be2 + i * DD, 1);
    }

    cudaMemsetAsync(out, 0, (size_t)BB * DD * sizeof(float));
    k_pool<<<(NN + 63) / 64, 256>>>(batch, out);
}

// round 6
// speedup vs baseline: 1.7499x; 1.1795x over previous
#include <cuda_runtime.h>
#include <cuda_bf16.h>
#include <cstdint>

// Problem constants
#define NN 50000
#define EE 800000
#define DD 128
#define LL 3
#define BB 256
#define BN_EPS 1e-5f
#define GEMM_GRID ((NN + 127) / 128)   // 391

// smem layout for tensor GEMM (bf16 tiles, 256B row pitch, xor-swizzled chunks)
#define SM_AHI 0
#define SM_ALO 32768
#define SM_BHI 65536
#define SM_BLO 98304
#define SMEM_TOT 131072

// ---------------- scratch (static device globals; no allocation) ----------------
__device__ float g_bufA[(size_t)NN * DD];   // z: raw pre-BN2 layer output
__device__ float g_bufB[(size_t)NN * DD];   // agg (activated input to GEMM1)
__device__ float g_bufC[(size_t)NN * DD];   // y: raw pre-BN1 hidden
__device__ int   g_deg[NN];
__device__ int   g_rowstart[NN];
__device__ int   g_cursor[NN];
__device__ int   g_col[EE];
__device__ int   g_incl[NN];
__device__ int   g_bsum[64];
__device__ int   g_bsumscan[64];
__device__ float g_partial_s[GEMM_GRID * DD];
__device__ float g_partial_q[GEMM_GRID * DD];
__device__ float g_scale1[DD];
__device__ float g_shift1[DD];
__device__ float g_scale2[DD];
__device__ float g_shift2[DD];
// prepared weights: [layer*2+which][hi/lo][32KB tile as uint4], swizzled [k][n] layout
__device__ uint4 g_wt[6][2][2048];

// ---------------- helpers ----------------
__device__ __forceinline__ uint32_t smem_u32(const void* p) {
    uint32_t a;
    asm("{ .reg .u64 t; cvta.to.shared.u64 t, %1; cvt.u32.u64 %0, t; }" : "=r"(a) : "l"(p));
    return a;
}

// byte offset inside a 128x128 bf16 tile (256B rows, 16B chunks, xor swizzle)
__device__ __forceinline__ uint32_t swz(int row, int col8) {
    int chunk = col8 >> 3;
    return (uint32_t)(row * 256 + ((chunk ^ (row & 7)) << 4));
}

// split fp32 pair -> bf16x2 hi + bf16x2 lo
__device__ __forceinline__ void split2(float a, float b, uint32_t& hi, uint32_t& lo) {
    __nv_bfloat162 h = __floats2bfloat162_rn(a, b);
    uint32_t uh = *reinterpret_cast<uint32_t*>(&h);
    float ra = __uint_as_float((uh & 0xFFFFu) << 16);
    float rb = __uint_as_float(uh & 0xFFFF0000u);
    __nv_bfloat162 l = __floats2bfloat162_rn(a - ra, b - rb);
    hi = uh;
    lo = *reinterpret_cast<uint32_t*>(&l);
}

__device__ __forceinline__ void ldsm_x4(uint32_t addr, uint32_t& r0, uint32_t& r1,
                                        uint32_t& r2, uint32_t& r3) {
    asm volatile("ldmatrix.sync.aligned.m8n8.x4.shared.b16 {%0,%1,%2,%3}, [%4];"
                 : "=r"(r0), "=r"(r1), "=r"(r2), "=r"(r3) : "r"(addr));
}

__device__ __forceinline__ void ldsm_x4_t(uint32_t addr, uint32_t& r0, uint32_t& r1,
                                          uint32_t& r2, uint32_t& r3) {
    asm volatile("ldmatrix.sync.aligned.m8n8.x4.trans.shared.b16 {%0,%1,%2,%3}, [%4];"
                 : "=r"(r0), "=r"(r1), "=r"(r2), "=r"(r3) : "r"(addr));
}

__device__ __forceinline__ void mma_bf16(float* c, uint32_t a0, uint32_t a1, uint32_t a2,
                                         uint32_t a3, uint32_t b0, uint32_t b1) {
    asm volatile(
        "mma.sync.aligned.m16n8k16.row.col.f32.bf16.bf16.f32 "
        "{%0,%1,%2,%3}, {%4,%5,%6,%7}, {%8,%9}, {%0,%1,%2,%3};"
        : "+f"(c[0]), "+f"(c[1]), "+f"(c[2]), "+f"(c[3])
        : "r"(a0), "r"(a1), "r"(a2), "r"(a3), "r"(b0), "r"(b1));
}

// ---------------- CSR build ----------------
__global__ void k_zero_deg() {
    int i = blockIdx.x * blockDim.x + threadIdx.x;
    if (i < NN) g_deg[i] = 0;
}

__global__ void k_hist(const int* __restrict__ dst) {
    int e = blockIdx.x * blockDim.x + threadIdx.x;
    if (e < EE) atomicAdd(&g_deg[dst[e]], 1);
}

__global__ void k_scan1() {
    __shared__ int s[1024];
    int t = threadIdx.x;
    int i = blockIdx.x * 1024 + t;
    int v = (i < NN) ? g_deg[i] : 0;
    s[t] = v;
    __syncthreads();
    #pragma unroll
    for (int off = 1; off < 1024; off <<= 1) {
        int add = (t >= off) ? s[t - off] : 0;
        __syncthreads();
        s[t] += add;
        __syncthreads();
    }
    if (i < NN) g_incl[i] = s[t];
    if (t == 1023) g_bsum[blockIdx.x] = s[t];
}

__global__ void k_scan2(int nblk) {
    __shared__ int s[64];
    int t = threadIdx.x;
    int v = (t < nblk) ? g_bsum[t] : 0;
    s[t] = v;
    __syncthreads();
    #pragma unroll
    for (int off = 1; off < 64; off <<= 1) {
        int add = (t >= off) ? s[t - off] : 0;
        __syncthreads();
        s[t] += add;
        __syncthreads();
    }
    g_bsumscan[t] = s[t];
}

__global__ void k_scan3() {
    int i = blockIdx.x * blockDim.x + threadIdx.x;
    if (i >= NN) return;
    int blk = i >> 10;
    int base = (blk > 0) ? g_bsumscan[blk - 1] : 0;
    int excl = base + g_incl[i] - g_deg[i];
    g_rowstart[i] = excl;
    g_cursor[i]   = excl;
}

__global__ void k_fill(const int* __restrict__ src, const int* __restrict__ dst) {
    int e = blockIdx.x * blockDim.x + threadIdx.x;
    if (e < EE) {
        int d = dst[e];
        int p = atomicAdd(&g_cursor[d], 1);
        g_col[p] = src[e];
    }
}

// ---------------- aggregation: one warp per node, CSR gather ----------------
__global__ void k_aggregate(const float* __restrict__ X, int apply) {
    int warp = (blockIdx.x * blockDim.x + threadIdx.x) >> 5;
    int lane = threadIdx.x & 31;
    if (warp >= NN) return;
    const float4* H4 = apply ? (const float4*)g_bufA : (const float4*)X;

    float4 a4 = make_float4(1.f, 1.f, 1.f, 1.f);
    float4 s4 = make_float4(0.f, 0.f, 0.f, 0.f);
    if (apply) {
        a4 = *(const float4*)&g_scale2[lane * 4];
        s4 = *(const float4*)&g_shift2[lane * 4];
    }

    float4 v = __ldg(&H4[(size_t)warp * 32 + lane]);
    float4 acc;
    if (apply) {
        acc.x = fmaxf(fmaf(v.x, a4.x, s4.x), 0.f);
        acc.y = fmaxf(fmaf(v.y, a4.y, s4.y), 0.f);
        acc.z = fmaxf(fmaf(v.z, a4.z, s4.z), 0.f);
        acc.w = fmaxf(fmaf(v.w, a4.w, s4.w), 0.f);
    } else {
        acc = v;
    }

    int s = g_rowstart[warp];
    int cnt = g_deg[warp];
    if (apply) {
        int j = 0;
        for (; j + 2 <= cnt; j += 2) {
            int s0 = g_col[s + j + 0];
            int s1 = g_col[s + j + 1];
            float4 v0 = __ldg(&H4[(size_t)s0 * 32 + lane]);
            float4 v1 = __ldg(&H4[(size_t)s1 * 32 + lane]);
            acc.x += fmaxf(fmaf(v0.x, a4.x, s4.x), 0.f) + fmaxf(fmaf(v1.x, a4.x, s4.x), 0.f);
            acc.y += fmaxf(fmaf(v0.y, a4.y, s4.y), 0.f) + fmaxf(fmaf(v1.y, a4.y, s4.y), 0.f);
            acc.z += fmaxf(fmaf(v0.z, a4.z, s4.z), 0.f) + fmaxf(fmaf(v1.z, a4.z, s4.z), 0.f);
            acc.w += fmaxf(fmaf(v0.w, a4.w, s4.w), 0.f) + fmaxf(fmaf(v1.w, a4.w, s4.w), 0.f);
        }
        for (; j < cnt; j++) {
            int s0 = g_col[s + j];
            float4 v0 = __ldg(&H4[(size_t)s0 * 32 + lane]);
            acc.x += fmaxf(fmaf(v0.x, a4.x, s4.x), 0.f);
            acc.y += fmaxf(fmaf(v0.y, a4.y, s4.y), 0.f);
            acc.z += fmaxf(fmaf(v0.z, a4.z, s4.z), 0.f);
            acc.w += fmaxf(fmaf(v0.w, a4.w, s4.w), 0.f);
        }
    } else {
        int j = 0;
        for (; j + 4 <= cnt; j += 4) {
            int s0 = g_col[s + j + 0];
            int s1 = g_col[s + j + 1];
            int s2 = g_col[s + j + 2];
            int s3 = g_col[s + j + 3];
            float4 v0 = __ldg(&H4[(size_t)s0 * 32 + lane]);
            float4 v1 = __ldg(&H4[(size_t)s1 * 32 + lane]);
            float4 v2 = __ldg(&H4[(size_t)s2 * 32 + lane]);
            float4 v3 = __ldg(&H4[(size_t)s3 * 32 + lane]);
            acc.x += v0.x + v1.x + v2.x + v3.x;
            acc.y += v0.y + v1.y + v2.y + v3.y;
            acc.z += v0.z + v1.z + v2.z + v3.z;
            acc.w += v0.w + v1.w + v2.w + v3.w;
        }
        for (; j < cnt; j++) {
            int s0 = g_col[s + j];
            float4 v0 = __ldg(&H4[(size_t)s0 * 32 + lane]);
            acc.x += v0.x; acc.y += v0.y; acc.z += v0.z; acc.w += v0.w;
        }
    }
    ((float4*)g_bufB)[(size_t)warp * 32 + lane] = acc;
}

// ---------------- W prep: bf16 split + swizzled [k][n] layout ----------------
__global__ void k_prep_w(const float* __restrict__ W1, const float* __restrict__ W2) {
    int idx = blockIdx.x;
    int layer = idx >> 1, which = idx & 1;
    const float* src = (which ? W2 : W1) + (size_t)layer * DD * DD;
    int t = threadIdx.x;
    int row = t >> 1, half = t & 1;    // row = k index

    char* dh = (char*)&g_wt[idx][0][0];
    char* dl = (char*)&g_wt[idx][1][0];
    const float4* s4 = (const float4*)(src + (size_t)row * 128 + half * 64);
    #pragma unroll
    for (int g = 0; g < 8; g++) {
        int cbase = half * 64 + g * 8;     // n index
        float4 u = __ldg(&s4[2 * g + 0]);
        float4 v = __ldg(&s4[2 * g + 1]);
        uint32_t h0, h1, h2, h3, l0, l1, l2, l3;
        split2(u.x, u.y, h0, l0);
        split2(u.z, u.w, h1, l1);
        split2(v.x, v.y, h2, l2);
        split2(v.z, v.w, h3, l3);
        uint32_t off = swz(row, cbase);
        *(uint4*)(dh + off) = make_uint4(h0, h1, h2, h3);
        *(uint4*)(dl + off) = make_uint4(l0, l1, l2, l3);
    }
}

// ---------------- tensor-core GEMM (mma.sync bf16 3-term) + fused BN stats ------
// which==0: A=g_bufB (no transform), C=g_bufC
// which==1: A=g_bufC with relu(scale1*v+shift1), C=g_bufA
__global__ __launch_bounds__(256, 1)
void k_gemm_mma(const float* __restrict__ bias, int widx, int which) {
    extern __shared__ char smem[];
    uint32_t sb = smem_u32(smem);
    const float* __restrict__ A = which ? g_bufC : g_bufB;
    float* __restrict__ C       = which ? g_bufA : g_bufC;

    int t = threadIdx.x;
    int wid = t >> 5, lane = t & 31;
    int block_row = blockIdx.x * 128;

    // --- B copy (pre-swizzled bytes) ---
    {
        const uint4* bh = &g_wt[widx][0][0];
        const uint4* bl = &g_wt[widx][1][0];
        uint4* sh4 = (uint4*)(smem + SM_BHI);
        uint4* sl4 = (uint4*)(smem + SM_BLO);
        #pragma unroll
        for (int i = 0; i < 8; i++) {
            sh4[t + 256 * i] = __ldg(&bh[t + 256 * i]);
            sl4[t + 256 * i] = __ldg(&bl[t + 256 * i]);
        }
    }

    // --- A convert: fp32 -> split bf16, swizzled ---
    {
        int row = t >> 1, half = t & 1;
        int gr = block_row + row;
        bool ok = (gr < NN);
        const float4* a4 = (const float4*)(A + (size_t)gr * 128 + half * 64);
        #pragma unroll
        for (int g = 0; g < 8; g++) {
            int cbase = half * 64 + g * 8;
            float4 u = ok ? __ldg(&a4[2 * g + 0]) : make_float4(0.f, 0.f, 0.f, 0.f);
            float4 v = ok ? __ldg(&a4[2 * g + 1]) : make_float4(0.f, 0.f, 0.f, 0.f);
            if (which) {
                float4 sa  = *(const float4*)&g_scale1[cbase];
                float4 sh4 = *(const float4*)&g_shift1[cbase];
                float4 sa2 = *(const float4*)&g_scale1[cbase + 4];
                float4 sh2 = *(const float4*)&g_shift1[cbase + 4];
                u.x = fmaxf(fmaf(u.x, sa.x, sh4.x), 0.f);
                u.y = fmaxf(fmaf(u.y, sa.y, sh4.y), 0.f);
                u.z = fmaxf(fmaf(u.z, sa.z, sh4.z), 0.f);
                u.w = fmaxf(fmaf(u.w, sa.w, sh4.w), 0.f);
                v.x = fmaxf(fmaf(v.x, sa2.x, sh2.x), 0.f);
                v.y = fmaxf(fmaf(v.y, sa2.y, sh2.y), 0.f);
                v.z = fmaxf(fmaf(v.z, sa2.z, sh2.z), 0.f);
                v.w = fmaxf(fmaf(v.w, sa2.w, sh2.w), 0.f);
            }
            uint32_t h0, h1, h2, h3, l0, l1, l2, l3;
            split2(u.x, u.y, h0, l0);
            split2(u.z, u.w, h1, l1);
            split2(v.x, v.y, h2, l2);
            split2(v.z, v.w, h3, l3);
            uint32_t off = swz(row, cbase);
            *(uint4*)(smem + SM_AHI + off) = make_uint4(h0, h1, h2, h3);
            *(uint4*)(smem + SM_ALO + off) = make_uint4(l0, l1, l2, l3);
        }
    }
    __syncthreads();

    // --- MMA mainloop: warp tile 32x64; single pass, all fragments per k-step ---
    int wm = (wid & 3) * 32;         // warp row offset in tile
    int wn = (wid >> 2) * 64;        // warp col offset in tile
    float acc[2][8][4];
    #pragma unroll
    for (int mt = 0; mt < 2; mt++)
        #pragma unroll
        for (int nt = 0; nt < 8; nt++)
            #pragma unroll
            for (int q = 0; q < 4; q++) acc[mt][nt][q] = 0.f;

    #pragma unroll
    for (int ks = 0; ks < 8; ks++) {
        uint32_t afh[2][4], afl[2][4];
        #pragma unroll
        for (int mt = 0; mt < 2; mt++) {
            int r = wm + mt * 16 + (lane & 15);
            int chunk = ks * 2 + (lane >> 4);
            uint32_t off = (uint32_t)(r * 256 + ((chunk ^ (r & 7)) << 4));
            ldsm_x4(sb + SM_AHI + off, afh[mt][0], afh[mt][1], afh[mt][2], afh[mt][3]);
            ldsm_x4(sb + SM_ALO + off, afl[mt][0], afl[mt][1], afl[mt][2], afl[mt][3]);
        }
        uint32_t bfh[8][2], bfl[8][2];
        #pragma unroll
        for (int np = 0; np < 4; np++) {
            int r = ks * 16 + (lane & 15);
            int chunk = ((wn + np * 16) >> 3) + (lane >> 4);
            uint32_t off = (uint32_t)(r * 256 + ((chunk ^ (r & 7)) << 4));
            uint32_t b0, b1, b2, b3;
            ldsm_x4_t(sb + SM_BHI + off, b0, b1, b2, b3);
            bfh[np * 2 + 0][0] = b0; bfh[np * 2 + 0][1] = b1;
            bfh[np * 2 + 1][0] = b2; bfh[np * 2 + 1][1] = b3;
            ldsm_x4_t(sb + SM_BLO + off, b0, b1, b2, b3);
            bfl[np * 2 + 0][0] = b0; bfl[np * 2 + 0][1] = b1;
            bfl[np * 2 + 1][0] = b2; bfl[np * 2 + 1][1] = b3;
        }
        #pragma unroll
        for (int mt = 0; mt < 2; mt++)
            #pragma unroll
            for (int nt = 0; nt < 8; nt++) {
                mma_bf16(acc[mt][nt], afh[mt][0], afh[mt][1], afh[mt][2], afh[mt][3],
                         bfh[nt][0], bfh[nt][1]);
                mma_bf16(acc[mt][nt], afh[mt][0], afh[mt][1], afh[mt][2], afh[mt][3],
                         bfl[nt][0], bfl[nt][1]);
                mma_bf16(acc[mt][nt], afl[mt][0], afl[mt][1], afl[mt][2], afl[mt][3],
                         bfh[nt][0], bfh[nt][1]);
            }
    }

    // --- epilogue: bias add + store + fused column stats ---
    int quad = lane >> 2, tq = lane & 3;
    float cs[8][2], cq[8][2];   // per-nt column partials (cols c, c+1)
    #pragma unroll
    for (int nt = 0; nt < 8; nt++) {
        cs[nt][0] = 0.f; cs[nt][1] = 0.f;
        cq[nt][0] = 0.f; cq[nt][1] = 0.f;
    }

    #pragma unroll
    for (int mt = 0; mt < 2; mt++) {
        int r0 = block_row + wm + mt * 16 + quad;
        bool ok0 = (r0 < NN), ok1 = (r0 + 8 < NN);
        #pragma unroll
        for (int nt = 0; nt < 8; nt++) {
            int c = wn + nt * 8 + tq * 2;
            float bx = __ldg(&bias[c]);
            float by = __ldg(&bias[c + 1]);
            float o0 = acc[mt][nt][0] + bx;
            float o1 = acc[mt][nt][1] + by;
            float o2 = acc[mt][nt][2] + bx;
            float o3 = acc[mt][nt][3] + by;
            if (ok0) {
                *(float2*)(C + (size_t)r0 * 128 + c) = make_float2(o0, o1);
                cs[nt][0] += o0; cq[nt][0] += o0 * o0;
                cs[nt][1] += o1; cq[nt][1] += o1 * o1;
            }
            if (ok1) {
                *(float2*)(C + (size_t)(r0 + 8) * 128 + c) = make_float2(o2, o3);
                cs[nt][0] += o2; cq[nt][0] += o2 * o2;
                cs[nt][1] += o3; cq[nt][1] += o3 * o3;
            }
        }
    }

    // reduce over the 8 quads (lanes with equal tq): xor 16, 8, 4
    #pragma unroll
    for (int nt = 0; nt < 8; nt++) {
        #pragma unroll
        for (int h = 0; h < 2; h++) {
            float s = cs[nt][h], q = cq[nt][h];
            s += __shfl_xor_sync(0xFFFFFFFFu, s, 16);
            q += __shfl_xor_sync(0xFFFFFFFFu, q, 16);
            s += __shfl_xor_sync(0xFFFFFFFFu, s, 8);
            q += __shfl_xor_sync(0xFFFFFFFFu, q, 8);
            s += __shfl_xor_sync(0xFFFFFFFFu, s, 4);
            q += __shfl_xor_sync(0xFFFFFFFFu, q, 4);
            cs[nt][h] = s; cq[nt][h] = q;
        }
    }

    // smem reuse for cross-warp reduction (A/B tiles are dead)
    __syncthreads();
    float* s_s = (float*)smem;             // [4][128]
    float* s_q = (float*)(smem + 2048);    // [4][128]
    if (quad == 0) {
        int rg = wid & 3;
        #pragma unroll
        for (int nt = 0; nt < 8; nt++) {
            int c = wn + nt * 8 + tq * 2;
            s_s[rg * 128 + c]     = cs[nt][0];
            s_s[rg * 128 + c + 1] = cs[nt][1];
            s_q[rg * 128 + c]     = cq[nt][0];
            s_q[rg * 128 + c + 1] = cq[nt][1];
        }
    }
    __syncthreads();
    if (t < 128) {
        float s = s_s[t] + s_s[128 + t] + s_s[256 + t] + s_s[384 + t];
        float q = s_q[t] + s_q[128 + t] + s_q[256 + t] + s_q[384 + t];
        g_partial_s[blockIdx.x * DD + t] = s;
        g_partial_q[blockIdx.x * DD + t] = q;
    }
}

// ---------------- BN finalize: reduce partials -> scale/shift ----------------
__global__ void k_finalize(const float* __restrict__ gamma, const float* __restrict__ beta,
                           int which) {
    __shared__ float ss[512];
    __shared__ float sq[512];
    int t = threadIdx.x;
    int c = t & 127, seg = t >> 7;
    float s = 0.f, q = 0.f;
    for (int b = seg; b < GEMM_GRID; b += 4) {
        s += g_partial_s[b * DD + c];
        q += g_partial_q[b * DD + c];
    }
    ss[t] = s; sq[t] = q;
    __syncthreads();
    if (seg == 0) {
        s = ss[c] + ss[c + 128] + ss[c + 256] + ss[c + 384];
        q = sq[c] + sq[c + 128] + sq[c + 256] + sq[c + 384];
        float inv_n = 1.f / (float)NN;
        float mean = s * inv_n;
        float var  = q * inv_n - mean * mean;
        float a = gamma[c] * rsqrtf(var + BN_EPS);
        float sh = beta[c] - mean * a;
        if (which) { g_scale2[c] = a; g_shift2[c] = sh; }
        else       { g_scale1[c] = a; g_shift1[c] = sh; }
    }
}

// ---------------- global add pool (batch sorted -> run-length accumulate) -------
__global__ void k_pool(const int* __restrict__ batch, float* __restrict__ out) {
    int c = threadIdx.x & 127;
    int half = threadIdx.x >> 7;
    int r0 = blockIdx.x * 64;
    int rend = min(r0 + 64, NN);
    float a = g_scale2[c];
    float s2 = g_shift2[c];
    int cur = -1;
    float acc = 0.f;
    for (int r = r0 + half; r < rend; r += 2) {
        int b = batch[r];
        if (b != cur) {
            if (cur >= 0) atomicAdd(&out[(size_t)cur * 128 + c], acc);
            cur = b;
            acc = 0.f;
        }
        float v = g_bufA[(size_t)r * 128 + c];
        acc += fmaxf(fmaf(v, a, s2), 0.f);
    }
    if (cur >= 0) atomicAdd(&out[(size_t)cur * 128 + c], acc);
}

// ---------------- launch ----------------
extern "C" void kernel_launch(void* const* d_in, const int* in_sizes, int n_in,
                              void* d_out, int out_size) {
    const float* x      = (const float*)d_in[0];
    const int*   eidx   = (const int*)d_in[1];
    const int*   batch  = (const int*)d_in[2];
    const float* W1     = (const float*)d_in[3];
    const float* b1     = (const float*)d_in[4];
    const float* g1     = (const float*)d_in[5];
    const float* be1    = (const float*)d_in[6];
    const float* W2     = (const float*)d_in[7];
    const float* b2     = (const float*)d_in[8];
    const float* g2     = (const float*)d_in[9];
    const float* be2    = (const float*)d_in[10];
    float* out = (float*)d_out;

    const int* src = eidx;
    const int* dst = eidx + EE;

    cudaFuncSetAttribute(k_gemm_mma, cudaFuncAttributeMaxDynamicSharedMemorySize, SMEM_TOT);

    const int nscanblk = (NN + 1023) / 1024;   // 49
    const int agg_grid = (NN + 7) / 8;         // 6250

    // --- weight prep + CSR build (reused for all 3 layers) ---
    k_prep_w<<<6, 256>>>(W1, W2);
    k_zero_deg<<<(NN + 255) / 256, 256>>>();
    k_hist<<<(EE + 255) / 256, 256>>>(dst);
    k_scan1<<<nscanblk, 1024>>>();
    k_scan2<<<1, 64>>>(nscanblk);
    k_scan3<<<(NN + 255) / 256, 256>>>();
    k_fill<<<(EE + 255) / 256, 256>>>(src, dst);

    for (int i = 0; i < LL; i++) {
        k_aggregate<<<agg_grid, 256>>>(x, i > 0 ? 1 : 0);
        k_gemm_mma<<<GEMM_GRID, 256, SMEM_TOT>>>(b1 + i * DD, i * 2 + 0, 0);
        k_finalize<<<1, 512>>>(g1 + i * DD, be1 + i * DD, 0);
        k_gemm_mma<<<GEMM_GRID, 256, SMEM_TOT>>>(b2 + i * DD, i * 2 + 1, 1);
        k_finalize<<<1, 512>>>(g2 + i * DD, be2 + i * DD, 1);
    }

    cudaMemsetAsync(out, 0, (size_t)BB * DD * sizeof(float));
    k_pool<<<(NN + 63) / 64, 256>>>(batch, out);
}